// round 2
// baseline (speedup 1.0000x reference)
#include <cuda_runtime.h>
#include <math.h>

// TV loss over x:(3, 4096, 4096) fp32 -> scalar sqrt(sum(dx^2)+sum(dy^2))
// dx = x[:, :-1, 1:] - x[:, :-1, :-1]
// dy = x[:, 1:, :-1] - x[:, :-1, :-1]

#define W 4096
#define H 4096
#define CH 3
#define ROWS_PER_BLOCK 32
#define THREADS 256            // 256 threads * 4 floats = 1024 columns per block

#define GRID_X (W / (THREADS * 4))                          // 4
#define GRID_Y ((H - 1 + ROWS_PER_BLOCK - 1) / ROWS_PER_BLOCK)  // 128
#define NUM_BLOCKS (GRID_X * GRID_Y * CH)                   // 1536

__device__ double g_partials[NUM_BLOCKS];

__global__ __launch_bounds__(THREADS) void tv_main_kernel(const float* __restrict__ x) {
    const int ch   = blockIdx.z;
    const int c4   = (blockIdx.x * THREADS + threadIdx.x) * 4;
    const int row0 = blockIdx.y * ROWS_PER_BLOCK;

    const float* __restrict__ base = x + (size_t)ch * W * H;

    int rend = row0 + ROWS_PER_BLOCK;
    if (rend > H - 1) rend = H - 1;     // last valid base row is H-2 = 4094

    const bool last_col = (c4 == W - 4);  // j=4095 excluded entirely

    float acc = 0.0f;

    const float* p = base + (size_t)row0 * W + c4;
    float4 cur    = *(const float4*)p;
    float  curext = last_col ? 0.0f : p[4];

    for (int i = row0; i < rend; ++i) {
        const float* pn = base + (size_t)(i + 1) * W + c4;
        float4 nxt    = *(const float4*)pn;
        float  nxtext = last_col ? 0.0f : pn[4];

        // horizontal dx at j = c4..c4+3
        float d0 = cur.y - cur.x;
        float d1 = cur.z - cur.y;
        float d2 = cur.w - cur.z;
        acc = fmaf(d0, d0, acc);
        acc = fmaf(d1, d1, acc);
        acc = fmaf(d2, d2, acc);
        if (!last_col) {
            float d3 = curext - cur.w;
            acc = fmaf(d3, d3, acc);
        }

        // vertical dy at j = c4..c4+3
        float e0 = nxt.x - cur.x;
        float e1 = nxt.y - cur.y;
        float e2 = nxt.z - cur.z;
        acc = fmaf(e0, e0, acc);
        acc = fmaf(e1, e1, acc);
        acc = fmaf(e2, e2, acc);
        if (!last_col) {
            float e3 = nxt.w - cur.w;
            acc = fmaf(e3, e3, acc);
        }

        cur = nxt;
        curext = nxtext;
    }

    // ---- block reduction ----
    #pragma unroll
    for (int off = 16; off > 0; off >>= 1)
        acc += __shfl_down_sync(0xFFFFFFFFu, acc, off);

    __shared__ float warp_sums[THREADS / 32];
    const int lane = threadIdx.x & 31;
    const int wid  = threadIdx.x >> 5;
    if (lane == 0) warp_sums[wid] = acc;
    __syncthreads();

    if (wid == 0) {
        float v = (lane < THREADS / 32) ? warp_sums[lane] : 0.0f;
        #pragma unroll
        for (int off = 4; off > 0; off >>= 1)
            v += __shfl_down_sync(0xFFFFFFFFu, v, off);
        if (lane == 0) {
            int bid = (blockIdx.z * gridDim.y + blockIdx.y) * gridDim.x + blockIdx.x;
            g_partials[bid] = (double)v;
        }
    }
}

__global__ __launch_bounds__(512) void tv_reduce_kernel(float* __restrict__ out) {
    double s = 0.0;
    for (int i = threadIdx.x; i < NUM_BLOCKS; i += 512)
        s += g_partials[i];

    #pragma unroll
    for (int off = 16; off > 0; off >>= 1)
        s += __shfl_down_sync(0xFFFFFFFFu, s, off);

    __shared__ double ws[16];
    const int lane = threadIdx.x & 31;
    const int wid  = threadIdx.x >> 5;
    if (lane == 0) ws[wid] = s;
    __syncthreads();

    if (wid == 0) {
        double v = (lane < 16) ? ws[lane] : 0.0;
        #pragma unroll
        for (int off = 8; off > 0; off >>= 1)
            v += __shfl_down_sync(0xFFFFFFFFu, v, off);
        if (lane == 0)
            out[0] = (float)sqrt(v);
    }
}

extern "C" void kernel_launch(void* const* d_in, const int* in_sizes, int n_in,
                              void* d_out, int out_size) {
    const float* x = (const float*)d_in[0];
    float* out = (float*)d_out;

    dim3 grid(GRID_X, GRID_Y, CH);
    tv_main_kernel<<<grid, THREADS>>>(x);
    tv_reduce_kernel<<<1, 512>>>(out);
}

// round 5
// speedup vs baseline: 1.0564x; 1.0564x over previous
#include <cuda_runtime.h>
#include <math.h>

// TV loss over x:(3, 4096, 4096) fp32 -> scalar sqrt(sum(dx^2)+sum(dy^2))
// Single fused kernel: tiled diff+square, block partials via atomicAdd(double),
// last block finalizes (sqrt -> out) and resets state for graph replay.

#define W 4096
#define H 4096
#define CH 3
#define ROWS_PER_BLOCK 64
#define THREADS 256            // 256 threads * 4 floats = 1024 columns per block

#define GRID_X (W / (THREADS * 4))                              // 4
#define GRID_Y ((H - 1 + ROWS_PER_BLOCK - 1) / ROWS_PER_BLOCK)  // 64
#define NUM_BLOCKS (GRID_X * GRID_Y * CH)                       // 768

// Accumulator stored as raw bits so we can atomicExch (read+reset) it.
__device__ unsigned long long g_acc_bits = 0ull;   // == __double_as_longlong(0.0)
__device__ unsigned int g_count = 0;

__global__ __launch_bounds__(THREADS) void tv_fused_kernel(const float* __restrict__ x,
                                                           float* __restrict__ out) {
    const int ch   = blockIdx.z;
    const int c4   = (blockIdx.x * THREADS + threadIdx.x) * 4;
    const int row0 = blockIdx.y * ROWS_PER_BLOCK;

    const float* __restrict__ base = x + (size_t)ch * W * H;

    int rend = row0 + ROWS_PER_BLOCK;
    if (rend > H - 1) rend = H - 1;     // last valid base row is H-2 = 4094

    const bool last_col = (c4 == W - 4);  // j=4095 excluded entirely

    float acc = 0.0f;

    const float* p = base + (size_t)row0 * W + c4;
    float4 cur    = *(const float4*)p;
    float  curext = last_col ? 0.0f : p[4];

    for (int i = row0; i < rend; ++i) {
        const float* pn = base + (size_t)(i + 1) * W + c4;
        float4 nxt    = *(const float4*)pn;
        float  nxtext = last_col ? 0.0f : pn[4];

        // horizontal dx at j = c4..c4+3
        float d0 = cur.y - cur.x;
        float d1 = cur.z - cur.y;
        float d2 = cur.w - cur.z;
        acc = fmaf(d0, d0, acc);
        acc = fmaf(d1, d1, acc);
        acc = fmaf(d2, d2, acc);
        if (!last_col) {
            float d3 = curext - cur.w;
            acc = fmaf(d3, d3, acc);
        }

        // vertical dy at j = c4..c4+3
        float e0 = nxt.x - cur.x;
        float e1 = nxt.y - cur.y;
        float e2 = nxt.z - cur.z;
        acc = fmaf(e0, e0, acc);
        acc = fmaf(e1, e1, acc);
        acc = fmaf(e2, e2, acc);
        if (!last_col) {
            float e3 = nxt.w - cur.w;
            acc = fmaf(e3, e3, acc);
        }

        cur = nxt;
        curext = nxtext;
    }

    // ---- block reduction ----
    #pragma unroll
    for (int off = 16; off > 0; off >>= 1)
        acc += __shfl_down_sync(0xFFFFFFFFu, acc, off);

    __shared__ float warp_sums[THREADS / 32];
    __shared__ bool is_last;
    const int lane = threadIdx.x & 31;
    const int wid  = threadIdx.x >> 5;
    if (lane == 0) warp_sums[wid] = acc;
    __syncthreads();

    if (wid == 0) {
        float v = (lane < THREADS / 32) ? warp_sums[lane] : 0.0f;
        #pragma unroll
        for (int off = 4; off > 0; off >>= 1)
            v += __shfl_down_sync(0xFFFFFFFFu, v, off);
        if (lane == 0) {
            atomicAdd((double*)&g_acc_bits, (double)v);
            __threadfence();
            unsigned int ticket = atomicInc(&g_count, NUM_BLOCKS - 1);
            is_last = (ticket == NUM_BLOCKS - 1);   // atomicInc wraps count back to 0
        }
    }
    __syncthreads();

    // Last block to arrive finalizes: read+reset the accumulator, write sqrt.
    if (is_last && threadIdx.x == 0) {
        unsigned long long bits = atomicExch(&g_acc_bits, 0ull);  // read & reset
        double total = __longlong_as_double(bits);
        out[0] = (float)sqrt(total);
    }
}

extern "C" void kernel_launch(void* const* d_in, const int* in_sizes, int n_in,
                              void* d_out, int out_size) {
    const float* x = (const float*)d_in[0];
    float* out = (float*)d_out;

    dim3 grid(GRID_X, GRID_Y, CH);
    tv_fused_kernel<<<grid, THREADS>>>(x, out);
}